// round 14
// baseline (speedup 1.0000x reference)
#include <cuda_runtime.h>
#include <stdint.h>

#define DIM 64
#define MAXN 50048
#define CAP 64
#define OVF_CAP 8192

// __device__ global scratch (sanctioned — no dynamic allocation). ~12.8 MB.
__device__ int g_cnt[MAXN];
__device__ int g_bucket[(size_t)MAXN * CAP];
__device__ int g_ovf_cnt;
__device__ int g_ovf[OVF_CAP];

__global__ void reset_kernel(int n_nodes) {
    int i = blockIdx.x * blockDim.x + threadIdx.x;
    if (i < n_nodes) g_cnt[i] = 0;
    if (i == 0) g_ovf_cnt = 0;
}

__global__ void place_kernel(const int* __restrict__ dst, int n_edges) {
    int e = blockIdx.x * blockDim.x + threadIdx.x;
    if (e >= n_edges) return;
    int d = dst[e];
    int pos = atomicAdd(&g_cnt[d], 1);
    if (pos < CAP) {
        g_bucket[(size_t)d * CAP + pos] = e;
    } else {
        int o = atomicAdd(&g_ovf_cnt, 1);
        if (o < OVF_CAP) g_ovf[o] = e;
    }
}

// One warp per node; 4 groups of 8 lanes, one edge per group per iteration.
// h accumulated in registers; one plain store per node (no atomics, no zeroing).
__global__ __launch_bounds__(256)
void node_kernel(const float* __restrict__ node_emb,
                 const float* __restrict__ edge_emb,
                 const int* __restrict__ src,
                 float* __restrict__ h_out,
                 float* __restrict__ dr_out,
                 int n_nodes) {
    int wid  = threadIdx.x >> 5;
    int node = blockIdx.x * 8 + wid;
    if (node >= n_nodes) return;          // whole warp exits together
    int lane = threadIdx.x & 31;
    int g    = lane >> 3;
    int l    = lane & 7;

    int cnt = g_cnt[node];
    if (cnt > CAP) cnt = CAP;

    const float4* tp = reinterpret_cast<const float4*>(node_emb + (size_t)node * DIM);
    float4 ta = tp[l];
    float4 tb = tp[l + 8];

    float4 aa = make_float4(0.f, 0.f, 0.f, 0.f);
    float4 ab = make_float4(0.f, 0.f, 0.f, 0.f);

    const int* bptr = g_bucket + (size_t)node * CAP;
    int iters = (cnt + 3) >> 2;          // uniform across the warp

    // software pipeline: edge id and src id one iteration ahead
    int  idx   = g;
    bool val   = idx < cnt;
    int  e_cur = val ? bptr[idx] : 0;
    int  s_cur = src[e_cur];

    for (int j = 0; j < iters; j++) {
        int  idx_n = idx + 4;
        bool val_n = idx_n < cnt;
        int  e_nxt = val_n ? bptr[idx_n] : 0;
        int  s_nxt = src[e_nxt];          // in flight during this iter's compute

        const float4* hp = reinterpret_cast<const float4*>(node_emb + (size_t)s_cur * DIM);
        const float4* rp = reinterpret_cast<const float4*>(edge_emb + (size_t)e_cur * DIM);
        float4 ha = hp[l];
        float4 hb = hp[l + 8];
        float4 ra = rp[l];
        float4 rb = rp[l + 8];

        float m0 = ha.x * ra.x, m1 = ha.y * ra.y, m2 = ha.z * ra.z, m3 = ha.w * ra.w;
        float n0 = hb.x * rb.x, n1 = hb.y * rb.y, n2 = hb.z * rb.z, n3 = hb.w * rb.w;

        float p = m0 * ta.x;
        p = fmaf(m1, ta.y, p);
        p = fmaf(m2, ta.z, p);
        p = fmaf(m3, ta.w, p);
        p = fmaf(n0, tb.x, p);
        p = fmaf(n1, tb.y, p);
        p = fmaf(n2, tb.z, p);
        p = fmaf(n3, tb.w, p);

        #pragma unroll
        for (int o = 4; o > 0; o >>= 1)
            p += __shfl_xor_sync(0xffffffffu, p, o, 8);

        if (val && l == 0) dr_out[e_cur] = p;

        float sig = 1.0f / (1.0f + __expf(-p));
        if (val) {
            aa.x = fmaf(sig, m0, aa.x);
            aa.y = fmaf(sig, m1, aa.y);
            aa.z = fmaf(sig, m2, aa.z);
            aa.w = fmaf(sig, m3, aa.w);
            ab.x = fmaf(sig, n0, ab.x);
            ab.y = fmaf(sig, n1, ab.y);
            ab.z = fmaf(sig, n2, ab.z);
            ab.w = fmaf(sig, n3, ab.w);
        }

        idx = idx_n; val = val_n; e_cur = e_nxt; s_cur = s_nxt;
    }

    // reduce accumulators across the 4 groups (lanes stride 8, 16)
    #pragma unroll
    for (int o = 8; o <= 16; o <<= 1) {
        aa.x += __shfl_xor_sync(0xffffffffu, aa.x, o);
        aa.y += __shfl_xor_sync(0xffffffffu, aa.y, o);
        aa.z += __shfl_xor_sync(0xffffffffu, aa.z, o);
        aa.w += __shfl_xor_sync(0xffffffffu, aa.w, o);
        ab.x += __shfl_xor_sync(0xffffffffu, ab.x, o);
        ab.y += __shfl_xor_sync(0xffffffffu, ab.y, o);
        ab.z += __shfl_xor_sync(0xffffffffu, ab.z, o);
        ab.w += __shfl_xor_sync(0xffffffffu, ab.w, o);
    }

    if (g == 0) {
        float4* op = reinterpret_cast<float4*>(h_out + (size_t)node * DIM);
        op[l]     = aa;
        op[l + 8] = ab;
    }
}

// Fallback for bucket-overflow edges (expected 0 for this input) — R9-style,
// RED-adds on top of the node_kernel's stored rows.
__global__ void ovf_kernel(const float* __restrict__ node_emb,
                           const float* __restrict__ edge_emb,
                           const int* __restrict__ src,
                           const int* __restrict__ dst,
                           float* __restrict__ h_out,
                           float* __restrict__ dr_out) {
    int n = g_ovf_cnt;
    if (n > OVF_CAP) n = OVF_CAP;
    int lane = threadIdx.x & 31;
    int l = lane & 7;
    int group   = (blockIdx.x * blockDim.x + threadIdx.x) >> 3;
    int ngroups = (gridDim.x * blockDim.x) >> 3;
    int iters = (n + ngroups - 1) / ngroups;   // uniform for all threads

    for (int t = 0; t < iters; t++) {
        int i = t * ngroups + group;
        bool v = i < n;
        int e = v ? g_ovf[i] : 0;
        int s = src[e];
        int d = dst[e];

        const float4* hp = reinterpret_cast<const float4*>(node_emb + (size_t)s * DIM);
        const float4* rp = reinterpret_cast<const float4*>(edge_emb + (size_t)e * DIM);
        const float4* tp = reinterpret_cast<const float4*>(node_emb + (size_t)d * DIM);
        float4 ha = hp[l], hb = hp[l + 8];
        float4 ra = rp[l], rb = rp[l + 8];
        float4 ta = tp[l], tb = tp[l + 8];

        float m0 = ha.x * ra.x, m1 = ha.y * ra.y, m2 = ha.z * ra.z, m3 = ha.w * ra.w;
        float n0 = hb.x * rb.x, n1 = hb.y * rb.y, n2 = hb.z * rb.z, n3 = hb.w * rb.w;

        float p = m0 * ta.x;
        p = fmaf(m1, ta.y, p);
        p = fmaf(m2, ta.z, p);
        p = fmaf(m3, ta.w, p);
        p = fmaf(n0, tb.x, p);
        p = fmaf(n1, tb.y, p);
        p = fmaf(n2, tb.z, p);
        p = fmaf(n3, tb.w, p);

        #pragma unroll
        for (int o = 4; o > 0; o >>= 1)
            p += __shfl_xor_sync(0xffffffffu, p, o, 8);

        if (v && l == 0) dr_out[e] = p;

        float sig = 1.0f / (1.0f + __expf(-p));
        if (v) {
            float* hd = h_out + (size_t)d * DIM + 4 * l;
            asm volatile("red.global.add.v4.f32 [%0], {%1, %2, %3, %4};"
                         :: "l"(hd), "f"(sig * m0), "f"(sig * m1),
                            "f"(sig * m2), "f"(sig * m3) : "memory");
            asm volatile("red.global.add.v4.f32 [%0], {%1, %2, %3, %4};"
                         :: "l"(hd + 32), "f"(sig * n0), "f"(sig * n1),
                            "f"(sig * n2), "f"(sig * n3) : "memory");
        }
    }
}

extern "C" void kernel_launch(void* const* d_in, const int* in_sizes, int n_in,
                              void* d_out, int out_size) {
    const float* node_emb = (const float*)d_in[0];
    const float* edge_emb = (const float*)d_in[1];
    const int*   src      = (const int*)d_in[2];
    const int*   dst      = (const int*)d_in[3];

    int n_nodes = in_sizes[0] / DIM;
    int n_edges = in_sizes[1] / DIM;

    float* h_out  = (float*)d_out;                                // [N, D]
    float* dr_out = (float*)d_out + (size_t)n_nodes * DIM;        // [E]

    reset_kernel<<<(n_nodes + 255) / 256, 256>>>(n_nodes);
    place_kernel<<<(n_edges + 255) / 256, 256>>>(dst, n_edges);

    int node_blocks = (n_nodes + 7) / 8;   // 8 warps/block, 1 node/warp
    node_kernel<<<node_blocks, 256>>>(node_emb, edge_emb, src,
                                      h_out, dr_out, n_nodes);

    ovf_kernel<<<4, 256>>>(node_emb, edge_emb, src, dst, h_out, dr_out);
}